// round 1
// baseline (speedup 1.0000x reference)
#include <cuda_runtime.h>
#include <math.h>

#define N_EDGES 32000
#define N_NODES 1600
#define HID     128
#define BASIS   512
#define DIN     768
#define M0      7
#define NSPH    49
#define NALL    29
#define WROW    (NSPH * NALL)   // 1421
#define OUT_PER_NODE (NSPH * HID) // 6272

// ---------------- device scratch (static globals, no allocation) ------------
static __device__ float g_x0[(size_t)N_EDGES * M0 * HID];  // 32000 x 7 x 128
static __device__ int   g_cnt[N_NODES];
static __device__ int   g_off[N_NODES + 1];
static __device__ int   g_cur[N_NODES];
static __device__ int   g_order[N_EDGES];
static __device__ int   g_jidx[M0];
static __device__ float g_jval[M0];

// ---------------- prep: zero counts + extract to_m column map ---------------
__global__ void k_prep(const float* __restrict__ to_m) {
    int idx = blockIdx.x * 1024 + threadIdx.x;
    if (idx < N_NODES) g_cnt[idx] = 0;
    if (idx == 0) {
        // to_m rows 0..6 are (near-)one-hot over 29 columns; find the column.
        for (int m = 0; m < M0; m++) {
            int best = 0; float bv = 0.f;
            for (int l = 0; l < NALL; l++) {
                float v = to_m[m * NALL + l];
                if (fabsf(v) > fabsf(bv)) { bv = v; best = l; }
            }
            g_jidx[m] = best;
            g_jval[m] = bv;
        }
    }
}

// ---------------- CSR build --------------------------------------------------
__global__ void k_count(const int* __restrict__ eidx) {
    int e = blockIdx.x * 256 + threadIdx.x;  // grid sized exactly
    atomicAdd(&g_cnt[eidx[N_EDGES + e]], 1);
}

__global__ void k_scan() {
    __shared__ int s[N_NODES];
    __shared__ int tot[256];
    const int t = threadIdx.x;
    for (int i = t; i < N_NODES; i += 256) s[i] = g_cnt[i];
    __syncthreads();
    const int base = t * 7;
    int sum = 0;
    for (int i = 0; i < 7; i++) {
        int idx = base + i;
        if (idx < N_NODES) { int v = s[idx]; s[idx] = sum; sum += v; }
    }
    tot[t] = sum;
    __syncthreads();
    if (t == 0) {
        int r = 0;
        for (int i = 0; i < 256; i++) { int v = tot[i]; tot[i] = r; r += v; }
        g_off[N_NODES] = r;
    }
    __syncthreads();
    const int b = tot[t];
    for (int i = 0; i < 7; i++) {
        int idx = base + i;
        if (idx < N_NODES) { int o = s[idx] + b; g_off[idx] = o; g_cur[idx] = o; }
    }
}

__global__ void k_scatter(const int* __restrict__ eidx) {
    int e = blockIdx.x * 256 + threadIdx.x;
    int n = eidx[N_EDGES + e];
    int p = atomicAdd(&g_cur[n], 1);
    g_order[p] = e;
}

// ---------------- fused MLP: x -> x0[e,7,128] --------------------------------
// Block: 32 edges, 128 threads. Thread (eg = t>>5, jq = t&31) owns edges
// eg*8..eg*8+7 and output channels jq*4..jq*4+3 (float4 accumulator per edge).
__global__ __launch_bounds__(128) void k_mlp(
    const float* __restrict__ dist, const int* __restrict__ eidx,
    const int* __restrict__ anum,
    const float* __restrict__ srcT, const float* __restrict__ tgtT,
    const float* __restrict__ w1, const float* __restrict__ b1,
    const float* __restrict__ g1, const float* __restrict__ be1,
    const float* __restrict__ w2, const float* __restrict__ b2,
    const float* __restrict__ g2, const float* __restrict__ be2,
    const float* __restrict__ w3, const float* __restrict__ b3)
{
    __shared__ float bufA[32 * 128];   // h1 (after LN+SiLU)
    __shared__ float bufB[32 * 128];   // x-chunk staging, then h2
    __shared__ float wsh[16 * 128];    // weight chunk [16 k][128 j]
    __shared__ int   asrc[32], atgt[32];

    const int t  = threadIdx.x;
    const int e0 = blockIdx.x * 32;
    if (t < 32) {
        int e = e0 + t;
        asrc[t] = anum[eidx[e]];
        atgt[t] = anum[eidx[N_EDGES + e]];
    }
    __syncthreads();

    const int jq = t & 31;
    const int eg = t >> 5;
    float4* wsh4 = (float4*)wsh;

    float4 acc[8];

    // ================= GEMM1: x[32,768] @ w1[768,128] =================
#pragma unroll
    for (int el = 0; el < 8; el++) acc[el] = make_float4(0.f, 0.f, 0.f, 0.f);

    for (int c0 = 0; c0 < DIN; c0 += 16) {
        // stage x chunk [32 e][16 k] into bufB (compact)
#pragma unroll
        for (int i = 0; i < 4; i++) {
            int idx = t + i * 128;           // 0..511
            int row = idx >> 4, col = idx & 15;
            float v;
            if (c0 < BASIS)       v = dist[(size_t)(e0 + row) * BASIS + c0 + col];
            else if (c0 < BASIS + HID) v = srcT[asrc[row] * HID + (c0 - BASIS) + col];
            else                  v = tgtT[atgt[row] * HID + (c0 - BASIS - HID) + col];
            bufB[row * 16 + col] = v;
        }
        // stage w1 chunk [16 k][128 j]
#pragma unroll
        for (int i = 0; i < 4; i++) {
            int idx4 = t + i * 128;
            int row = idx4 >> 5, col4 = idx4 & 31;
            wsh4[idx4] = *(const float4*)(w1 + (size_t)(c0 + row) * HID + col4 * 4);
        }
        __syncthreads();
#pragma unroll
        for (int kk = 0; kk < 16; kk++) {
            float4 w4 = wsh4[kk * 32 + jq];
#pragma unroll
            for (int el = 0; el < 8; el++) {
                float xv = bufB[(eg * 8 + el) * 16 + kk];
                acc[el].x = fmaf(xv, w4.x, acc[el].x);
                acc[el].y = fmaf(xv, w4.y, acc[el].y);
                acc[el].z = fmaf(xv, w4.z, acc[el].z);
                acc[el].w = fmaf(xv, w4.w, acc[el].w);
            }
        }
        __syncthreads();
    }

    // epilogue 1: bias + LN + SiLU -> bufA
    {
        float4 bv  = *(const float4*)(b1  + jq * 4);
        float4 gv  = *(const float4*)(g1  + jq * 4);
        float4 bev = *(const float4*)(be1 + jq * 4);
#pragma unroll
        for (int el = 0; el < 8; el++) {
            float4 a = acc[el];
            a.x += bv.x; a.y += bv.y; a.z += bv.z; a.w += bv.w;
            float s = a.x + a.y + a.z + a.w;
            float q = a.x * a.x + a.y * a.y + a.z * a.z + a.w * a.w;
#pragma unroll
            for (int o = 16; o > 0; o >>= 1) {
                s += __shfl_xor_sync(0xffffffffu, s, o);
                q += __shfl_xor_sync(0xffffffffu, q, o);
            }
            float mu  = s * (1.f / 128.f);
            float var = q * (1.f / 128.f) - mu * mu;
            float rs  = rsqrtf(var + 1e-5f);
            float4 r;
            r.x = (a.x - mu) * rs * gv.x + bev.x;
            r.y = (a.y - mu) * rs * gv.y + bev.y;
            r.z = (a.z - mu) * rs * gv.z + bev.z;
            r.w = (a.w - mu) * rs * gv.w + bev.w;
            r.x = r.x / (1.f + __expf(-r.x));
            r.y = r.y / (1.f + __expf(-r.y));
            r.z = r.z / (1.f + __expf(-r.z));
            r.w = r.w / (1.f + __expf(-r.w));
            ((float4*)bufA)[(eg * 8 + el) * 32 + jq] = r;
        }
    }

    // ================= GEMM2: h1[32,128] @ w2[128,128] =================
#pragma unroll
    for (int el = 0; el < 8; el++) acc[el] = make_float4(0.f, 0.f, 0.f, 0.f);
    for (int c0 = 0; c0 < HID; c0 += 16) {
        __syncthreads();   // protect wsh from previous readers; also fences bufA writes
#pragma unroll
        for (int i = 0; i < 4; i++) {
            int idx4 = t + i * 128;
            int row = idx4 >> 5, col4 = idx4 & 31;
            wsh4[idx4] = *(const float4*)(w2 + (size_t)(c0 + row) * HID + col4 * 4);
        }
        __syncthreads();
#pragma unroll
        for (int kk = 0; kk < 16; kk++) {
            float4 w4 = wsh4[kk * 32 + jq];
#pragma unroll
            for (int el = 0; el < 8; el++) {
                float xv = bufA[(eg * 8 + el) * 128 + c0 + kk];
                acc[el].x = fmaf(xv, w4.x, acc[el].x);
                acc[el].y = fmaf(xv, w4.y, acc[el].y);
                acc[el].z = fmaf(xv, w4.z, acc[el].z);
                acc[el].w = fmaf(xv, w4.w, acc[el].w);
            }
        }
    }
    __syncthreads();

    // epilogue 2: bias + LN + SiLU -> bufB
    {
        float4 bv  = *(const float4*)(b2  + jq * 4);
        float4 gv  = *(const float4*)(g2  + jq * 4);
        float4 bev = *(const float4*)(be2 + jq * 4);
#pragma unroll
        for (int el = 0; el < 8; el++) {
            float4 a = acc[el];
            a.x += bv.x; a.y += bv.y; a.z += bv.z; a.w += bv.w;
            float s = a.x + a.y + a.z + a.w;
            float q = a.x * a.x + a.y * a.y + a.z * a.z + a.w * a.w;
#pragma unroll
            for (int o = 16; o > 0; o >>= 1) {
                s += __shfl_xor_sync(0xffffffffu, s, o);
                q += __shfl_xor_sync(0xffffffffu, q, o);
            }
            float mu  = s * (1.f / 128.f);
            float var = q * (1.f / 128.f) - mu * mu;
            float rs  = rsqrtf(var + 1e-5f);
            float4 r;
            r.x = (a.x - mu) * rs * gv.x + bev.x;
            r.y = (a.y - mu) * rs * gv.y + bev.y;
            r.z = (a.z - mu) * rs * gv.z + bev.z;
            r.w = (a.w - mu) * rs * gv.w + bev.w;
            r.x = r.x / (1.f + __expf(-r.x));
            r.y = r.y / (1.f + __expf(-r.y));
            r.z = r.z / (1.f + __expf(-r.z));
            r.w = r.w / (1.f + __expf(-r.w));
            ((float4*)bufB)[(eg * 8 + el) * 32 + jq] = r;
        }
    }

    // ================= GEMM3: h2[32,128] @ w3[128, 7*128] =================
    for (int m = 0; m < M0; m++) {
#pragma unroll
        for (int el = 0; el < 8; el++) acc[el] = make_float4(0.f, 0.f, 0.f, 0.f);
        for (int c0 = 0; c0 < HID; c0 += 16) {
            __syncthreads();
#pragma unroll
            for (int i = 0; i < 4; i++) {
                int idx4 = t + i * 128;
                int row = idx4 >> 5, col4 = idx4 & 31;
                wsh4[idx4] = *(const float4*)(w3 + (size_t)(c0 + row) * (M0 * HID)
                                              + m * HID + col4 * 4);
            }
            __syncthreads();
#pragma unroll
            for (int kk = 0; kk < 16; kk++) {
                float4 w4 = wsh4[kk * 32 + jq];
#pragma unroll
                for (int el = 0; el < 8; el++) {
                    float xv = bufB[(eg * 8 + el) * 128 + c0 + kk];
                    acc[el].x = fmaf(xv, w4.x, acc[el].x);
                    acc[el].y = fmaf(xv, w4.y, acc[el].y);
                    acc[el].z = fmaf(xv, w4.z, acc[el].z);
                    acc[el].w = fmaf(xv, w4.w, acc[el].w);
                }
            }
        }
        // epilogue: bias + store x0
        float4 b3v = *(const float4*)(b3 + m * HID + jq * 4);
#pragma unroll
        for (int el = 0; el < 8; el++) {
            float4 a = acc[el];
            a.x += b3v.x; a.y += b3v.y; a.z += b3v.z; a.w += b3v.w;
            size_t e = (size_t)(e0 + eg * 8 + el);
            ((float4*)g_x0)[(e * M0 + m) * 32 + jq] = a;
        }
    }
}

// ---------------- node-centric wigner contraction + reduce -------------------
// out[n,i,c] = (1/RESCALE) * sum_{e: tgt(e)=n} sum_m wig[e,i,J_m]*jval_m*x0[e,m,c]
__global__ __launch_bounds__(128) void k_node(
    const float* __restrict__ wig, float* __restrict__ out)
{
    __shared__ float wsh[WROW];   // one edge's full wigner block [49][29]
    const int n = blockIdx.x;
    const int t = threadIdx.x;    // channel c

    int   jml[M0];
    float jvl[M0];
#pragma unroll
    for (int m = 0; m < M0; m++) { jml[m] = g_jidx[m]; jvl[m] = g_jval[m]; }

    float acc[NSPH];
#pragma unroll
    for (int i = 0; i < NSPH; i++) acc[i] = 0.f;

    const int s0 = g_off[n], s1 = g_off[n + 1];
    for (int ii = s0; ii < s1; ii++) {
        const int e = g_order[ii];
        __syncthreads();   // prior iteration's reads of wsh done
        for (int i = t; i < WROW; i += 128) wsh[i] = wig[(size_t)e * WROW + i];
        float x0v[M0];
#pragma unroll
        for (int m = 0; m < M0; m++)
            x0v[m] = g_x0[((size_t)e * M0 + m) * HID + t] * jvl[m];
        __syncthreads();
#pragma unroll
        for (int i = 0; i < NSPH; i++) {
            float r = wsh[i * NALL + jml[0]] * x0v[0];
#pragma unroll
            for (int m = 1; m < M0; m++)
                r = fmaf(wsh[i * NALL + jml[m]], x0v[m], r);
            acc[i] += r;
        }
    }

    const float sc = (float)(1.0 / 23.395238876342773);
#pragma unroll
    for (int i = 0; i < NSPH; i++)
        out[(size_t)n * OUT_PER_NODE + i * HID + t] = acc[i] * sc;
}

// ---------------- launch -----------------------------------------------------
extern "C" void kernel_launch(void* const* d_in, const int* in_sizes, int n_in,
                              void* d_out, int out_size)
{
    (void)in_sizes; (void)n_in; (void)out_size;
    const int*   anum = (const int*)  d_in[0];
    const float* dist = (const float*)d_in[1];
    const int*   eidx = (const int*)  d_in[2];
    const float* srcT = (const float*)d_in[3];
    const float* tgtT = (const float*)d_in[4];
    const float* w1   = (const float*)d_in[5];
    const float* b1   = (const float*)d_in[6];
    const float* g1   = (const float*)d_in[7];
    const float* be1  = (const float*)d_in[8];
    const float* w2   = (const float*)d_in[9];
    const float* b2   = (const float*)d_in[10];
    const float* g2   = (const float*)d_in[11];
    const float* be2  = (const float*)d_in[12];
    const float* w3   = (const float*)d_in[13];
    const float* b3   = (const float*)d_in[14];
    const float* to_m = (const float*)d_in[15];
    const float* wig  = (const float*)d_in[16];
    float* out = (float*)d_out;

    k_prep<<<2, 1024>>>(to_m);
    k_count<<<N_EDGES / 256, 256>>>(eidx);
    k_scan<<<1, 256>>>();
    k_scatter<<<N_EDGES / 256, 256>>>(eidx);
    k_mlp<<<N_EDGES / 32, 128>>>(dist, eidx, anum, srcT, tgtT,
                                 w1, b1, g1, be1, w2, b2, g2, be2, w3, b3);
    k_node<<<N_NODES, 128>>>(wig, out);
}

// round 2
// speedup vs baseline: 1.0009x; 1.0009x over previous
#include <cuda_runtime.h>
#include <math.h>

#define N_EDGES 32000
#define N_NODES 1600
#define HID     128
#define BASIS   512
#define DIN     768
#define M0      7
#define NSPH    49
#define NALL    29
#define WROW    (NSPH * NALL)   // 1421
#define OUT_PER_NODE (NSPH * HID) // 6272

// ---------------- device scratch (static globals, no allocation) ------------
static __device__ float g_x0[(size_t)N_EDGES * M0 * HID];  // 32000 x 7 x 128
static __device__ int   g_cnt[N_NODES];
static __device__ int   g_off[N_NODES + 1];
static __device__ int   g_cur[N_NODES];
static __device__ int   g_order[N_EDGES];
static __device__ int   g_jidx[M0];
static __device__ float g_jval[M0];

// ---------------- prep: zero counts + extract to_m column map ---------------
__global__ void k_prep(const float* __restrict__ to_m) {
    int idx = blockIdx.x * 1024 + threadIdx.x;
    if (idx < N_NODES) g_cnt[idx] = 0;
    if (idx == 0) {
        // to_m rows 0..6 are (near-)one-hot over 29 columns; find the column.
        for (int m = 0; m < M0; m++) {
            int best = 0; float bv = 0.f;
            for (int l = 0; l < NALL; l++) {
                float v = to_m[m * NALL + l];
                if (fabsf(v) > fabsf(bv)) { bv = v; best = l; }
            }
            g_jidx[m] = best;
            g_jval[m] = bv;
        }
    }
}

// ---------------- CSR build --------------------------------------------------
__global__ void k_count(const int* __restrict__ eidx) {
    int e = blockIdx.x * 256 + threadIdx.x;  // grid sized exactly
    atomicAdd(&g_cnt[eidx[N_EDGES + e]], 1);
}

__global__ void k_scan() {
    __shared__ int s[N_NODES];
    __shared__ int tot[256];
    const int t = threadIdx.x;
    for (int i = t; i < N_NODES; i += 256) s[i] = g_cnt[i];
    __syncthreads();
    const int base = t * 7;
    int sum = 0;
    for (int i = 0; i < 7; i++) {
        int idx = base + i;
        if (idx < N_NODES) { int v = s[idx]; s[idx] = sum; sum += v; }
    }
    tot[t] = sum;
    __syncthreads();
    if (t == 0) {
        int r = 0;
        for (int i = 0; i < 256; i++) { int v = tot[i]; tot[i] = r; r += v; }
        g_off[N_NODES] = r;
    }
    __syncthreads();
    const int b = tot[t];
    for (int i = 0; i < 7; i++) {
        int idx = base + i;
        if (idx < N_NODES) { int o = s[idx] + b; g_off[idx] = o; g_cur[idx] = o; }
    }
}

__global__ void k_scatter(const int* __restrict__ eidx) {
    int e = blockIdx.x * 256 + threadIdx.x;
    int n = eidx[N_EDGES + e];
    int p = atomicAdd(&g_cur[n], 1);
    g_order[p] = e;
}

// ---------------- fused MLP: x -> x0[e,7,128] --------------------------------
// Block: 32 edges, 128 threads. Thread (eg = t>>5, jq = t&31) owns edges
// eg*8..eg*8+7 and output channels jq*4..jq*4+3 (float4 accumulator per edge).
__global__ __launch_bounds__(128) void k_mlp(
    const float* __restrict__ dist, const int* __restrict__ eidx,
    const int* __restrict__ anum,
    const float* __restrict__ srcT, const float* __restrict__ tgtT,
    const float* __restrict__ w1, const float* __restrict__ b1,
    const float* __restrict__ g1, const float* __restrict__ be1,
    const float* __restrict__ w2, const float* __restrict__ b2,
    const float* __restrict__ g2, const float* __restrict__ be2,
    const float* __restrict__ w3, const float* __restrict__ b3)
{
    __shared__ float bufA[32 * 128];   // h1 (after LN+SiLU)
    __shared__ float bufB[32 * 128];   // x-chunk staging, then h2
    __shared__ float wsh[16 * 128];    // weight chunk [16 k][128 j]
    __shared__ int   asrc[32], atgt[32];

    const int t  = threadIdx.x;
    const int e0 = blockIdx.x * 32;
    if (t < 32) {
        int e = e0 + t;
        asrc[t] = anum[eidx[e]];
        atgt[t] = anum[eidx[N_EDGES + e]];
    }
    __syncthreads();

    const int jq = t & 31;
    const int eg = t >> 5;
    float4* wsh4 = (float4*)wsh;

    float4 acc[8];

    // ================= GEMM1: x[32,768] @ w1[768,128] =================
#pragma unroll
    for (int el = 0; el < 8; el++) acc[el] = make_float4(0.f, 0.f, 0.f, 0.f);

    for (int c0 = 0; c0 < DIN; c0 += 16) {
        // stage x chunk [32 e][16 k] into bufB (compact)
#pragma unroll
        for (int i = 0; i < 4; i++) {
            int idx = t + i * 128;           // 0..511
            int row = idx >> 4, col = idx & 15;
            float v;
            if (c0 < BASIS)       v = dist[(size_t)(e0 + row) * BASIS + c0 + col];
            else if (c0 < BASIS + HID) v = srcT[asrc[row] * HID + (c0 - BASIS) + col];
            else                  v = tgtT[atgt[row] * HID + (c0 - BASIS - HID) + col];
            bufB[row * 16 + col] = v;
        }
        // stage w1 chunk [16 k][128 j]
#pragma unroll
        for (int i = 0; i < 4; i++) {
            int idx4 = t + i * 128;
            int row = idx4 >> 5, col4 = idx4 & 31;
            wsh4[idx4] = *(const float4*)(w1 + (size_t)(c0 + row) * HID + col4 * 4);
        }
        __syncthreads();
#pragma unroll
        for (int kk = 0; kk < 16; kk++) {
            float4 w4 = wsh4[kk * 32 + jq];
#pragma unroll
            for (int el = 0; el < 8; el++) {
                float xv = bufB[(eg * 8 + el) * 16 + kk];
                acc[el].x = fmaf(xv, w4.x, acc[el].x);
                acc[el].y = fmaf(xv, w4.y, acc[el].y);
                acc[el].z = fmaf(xv, w4.z, acc[el].z);
                acc[el].w = fmaf(xv, w4.w, acc[el].w);
            }
        }
        __syncthreads();
    }

    // epilogue 1: bias + LN + SiLU -> bufA
    {
        float4 bv  = *(const float4*)(b1  + jq * 4);
        float4 gv  = *(const float4*)(g1  + jq * 4);
        float4 bev = *(const float4*)(be1 + jq * 4);
#pragma unroll
        for (int el = 0; el < 8; el++) {
            float4 a = acc[el];
            a.x += bv.x; a.y += bv.y; a.z += bv.z; a.w += bv.w;
            float s = a.x + a.y + a.z + a.w;
            float q = a.x * a.x + a.y * a.y + a.z * a.z + a.w * a.w;
#pragma unroll
            for (int o = 16; o > 0; o >>= 1) {
                s += __shfl_xor_sync(0xffffffffu, s, o);
                q += __shfl_xor_sync(0xffffffffu, q, o);
            }
            float mu  = s * (1.f / 128.f);
            float var = q * (1.f / 128.f) - mu * mu;
            float rs  = rsqrtf(var + 1e-5f);
            float4 r;
            r.x = (a.x - mu) * rs * gv.x + bev.x;
            r.y = (a.y - mu) * rs * gv.y + bev.y;
            r.z = (a.z - mu) * rs * gv.z + bev.z;
            r.w = (a.w - mu) * rs * gv.w + bev.w;
            r.x = r.x / (1.f + __expf(-r.x));
            r.y = r.y / (1.f + __expf(-r.y));
            r.z = r.z / (1.f + __expf(-r.z));
            r.w = r.w / (1.f + __expf(-r.w));
            ((float4*)bufA)[(eg * 8 + el) * 32 + jq] = r;
        }
    }

    // ================= GEMM2: h1[32,128] @ w2[128,128] =================
#pragma unroll
    for (int el = 0; el < 8; el++) acc[el] = make_float4(0.f, 0.f, 0.f, 0.f);
    for (int c0 = 0; c0 < HID; c0 += 16) {
        __syncthreads();   // protect wsh from previous readers; also fences bufA writes
#pragma unroll
        for (int i = 0; i < 4; i++) {
            int idx4 = t + i * 128;
            int row = idx4 >> 5, col4 = idx4 & 31;
            wsh4[idx4] = *(const float4*)(w2 + (size_t)(c0 + row) * HID + col4 * 4);
        }
        __syncthreads();
#pragma unroll
        for (int kk = 0; kk < 16; kk++) {
            float4 w4 = wsh4[kk * 32 + jq];
#pragma unroll
            for (int el = 0; el < 8; el++) {
                float xv = bufA[(eg * 8 + el) * 128 + c0 + kk];
                acc[el].x = fmaf(xv, w4.x, acc[el].x);
                acc[el].y = fmaf(xv, w4.y, acc[el].y);
                acc[el].z = fmaf(xv, w4.z, acc[el].z);
                acc[el].w = fmaf(xv, w4.w, acc[el].w);
            }
        }
    }
    __syncthreads();

    // epilogue 2: bias + LN + SiLU -> bufB
    {
        float4 bv  = *(const float4*)(b2  + jq * 4);
        float4 gv  = *(const float4*)(g2  + jq * 4);
        float4 bev = *(const float4*)(be2 + jq * 4);
#pragma unroll
        for (int el = 0; el < 8; el++) {
            float4 a = acc[el];
            a.x += bv.x; a.y += bv.y; a.z += bv.z; a.w += bv.w;
            float s = a.x + a.y + a.z + a.w;
            float q = a.x * a.x + a.y * a.y + a.z * a.z + a.w * a.w;
#pragma unroll
            for (int o = 16; o > 0; o >>= 1) {
                s += __shfl_xor_sync(0xffffffffu, s, o);
                q += __shfl_xor_sync(0xffffffffu, q, o);
            }
            float mu  = s * (1.f / 128.f);
            float var = q * (1.f / 128.f) - mu * mu;
            float rs  = rsqrtf(var + 1e-5f);
            float4 r;
            r.x = (a.x - mu) * rs * gv.x + bev.x;
            r.y = (a.y - mu) * rs * gv.y + bev.y;
            r.z = (a.z - mu) * rs * gv.z + bev.z;
            r.w = (a.w - mu) * rs * gv.w + bev.w;
            r.x = r.x / (1.f + __expf(-r.x));
            r.y = r.y / (1.f + __expf(-r.y));
            r.z = r.z / (1.f + __expf(-r.z));
            r.w = r.w / (1.f + __expf(-r.w));
            ((float4*)bufB)[(eg * 8 + el) * 32 + jq] = r;
        }
    }

    // ================= GEMM3: h2[32,128] @ w3[128, 7*128] =================
    for (int m = 0; m < M0; m++) {
#pragma unroll
        for (int el = 0; el < 8; el++) acc[el] = make_float4(0.f, 0.f, 0.f, 0.f);
        for (int c0 = 0; c0 < HID; c0 += 16) {
            __syncthreads();
#pragma unroll
            for (int i = 0; i < 4; i++) {
                int idx4 = t + i * 128;
                int row = idx4 >> 5, col4 = idx4 & 31;
                wsh4[idx4] = *(const float4*)(w3 + (size_t)(c0 + row) * (M0 * HID)
                                              + m * HID + col4 * 4);
            }
            __syncthreads();
#pragma unroll
            for (int kk = 0; kk < 16; kk++) {
                float4 w4 = wsh4[kk * 32 + jq];
#pragma unroll
                for (int el = 0; el < 8; el++) {
                    float xv = bufB[(eg * 8 + el) * 128 + c0 + kk];
                    acc[el].x = fmaf(xv, w4.x, acc[el].x);
                    acc[el].y = fmaf(xv, w4.y, acc[el].y);
                    acc[el].z = fmaf(xv, w4.z, acc[el].z);
                    acc[el].w = fmaf(xv, w4.w, acc[el].w);
                }
            }
        }
        // epilogue: bias + store x0
        float4 b3v = *(const float4*)(b3 + m * HID + jq * 4);
#pragma unroll
        for (int el = 0; el < 8; el++) {
            float4 a = acc[el];
            a.x += b3v.x; a.y += b3v.y; a.z += b3v.z; a.w += b3v.w;
            size_t e = (size_t)(e0 + eg * 8 + el);
            ((float4*)g_x0)[(e * M0 + m) * 32 + jq] = a;
        }
    }
}

// ---------------- node-centric wigner contraction + reduce -------------------
// out[n,i,c] = (1/RESCALE) * sum_{e: tgt(e)=n} sum_m wig[e,i,J_m]*jval_m*x0[e,m,c]
__global__ __launch_bounds__(128) void k_node(
    const float* __restrict__ wig, float* __restrict__ out)
{
    __shared__ float wsh[WROW];   // one edge's full wigner block [49][29]
    const int n = blockIdx.x;
    const int t = threadIdx.x;    // channel c

    int   jml[M0];
    float jvl[M0];
#pragma unroll
    for (int m = 0; m < M0; m++) { jml[m] = g_jidx[m]; jvl[m] = g_jval[m]; }

    float acc[NSPH];
#pragma unroll
    for (int i = 0; i < NSPH; i++) acc[i] = 0.f;

    const int s0 = g_off[n], s1 = g_off[n + 1];
    for (int ii = s0; ii < s1; ii++) {
        const int e = g_order[ii];
        __syncthreads();   // prior iteration's reads of wsh done
        for (int i = t; i < WROW; i += 128) wsh[i] = wig[(size_t)e * WROW + i];
        float x0v[M0];
#pragma unroll
        for (int m = 0; m < M0; m++)
            x0v[m] = g_x0[((size_t)e * M0 + m) * HID + t] * jvl[m];
        __syncthreads();
#pragma unroll
        for (int i = 0; i < NSPH; i++) {
            float r = wsh[i * NALL + jml[0]] * x0v[0];
#pragma unroll
            for (int m = 1; m < M0; m++)
                r = fmaf(wsh[i * NALL + jml[m]], x0v[m], r);
            acc[i] += r;
        }
    }

    const float sc = (float)(1.0 / 23.395238876342773);
#pragma unroll
    for (int i = 0; i < NSPH; i++)
        out[(size_t)n * OUT_PER_NODE + i * HID + t] = acc[i] * sc;
}

// ---------------- launch -----------------------------------------------------
extern "C" void kernel_launch(void* const* d_in, const int* in_sizes, int n_in,
                              void* d_out, int out_size)
{
    (void)in_sizes; (void)n_in; (void)out_size;
    const int*   anum = (const int*)  d_in[0];
    const float* dist = (const float*)d_in[1];
    const int*   eidx = (const int*)  d_in[2];
    const float* srcT = (const float*)d_in[3];
    const float* tgtT = (const float*)d_in[4];
    const float* w1   = (const float*)d_in[5];
    const float* b1   = (const float*)d_in[6];
    const float* g1   = (const float*)d_in[7];
    const float* be1  = (const float*)d_in[8];
    const float* w2   = (const float*)d_in[9];
    const float* b2   = (const float*)d_in[10];
    const float* g2   = (const float*)d_in[11];
    const float* be2  = (const float*)d_in[12];
    const float* w3   = (const float*)d_in[13];
    const float* b3   = (const float*)d_in[14];
    const float* to_m = (const float*)d_in[15];
    const float* wig  = (const float*)d_in[16];
    float* out = (float*)d_out;

    k_prep<<<2, 1024>>>(to_m);
    k_count<<<N_EDGES / 256, 256>>>(eidx);
    k_scan<<<1, 256>>>();
    k_scatter<<<N_EDGES / 256, 256>>>(eidx);
    k_mlp<<<N_EDGES / 32, 128>>>(dist, eidx, anum, srcT, tgtT,
                                 w1, b1, g1, be1, w2, b2, g2, be2, w3, b3);
    k_node<<<N_NODES, 128>>>(wig, out);
}

// round 8
// speedup vs baseline: 1.4174x; 1.4162x over previous
#include <cuda_runtime.h>
#include <math.h>
#include <stdint.h>

#define N_EDGES 32000
#define N_NODES 1600
#define HID     128
#define DIN     768
#define M0      7
#define NSPH    49
#define NALL    29
#define WROW    (NSPH * NALL)      // 1421
#define OUT_PER_NODE (NSPH * HID)  // 6272

// ---------------- device scratch ---------------------------------------------
static __device__ float g_x0[(size_t)N_EDGES * M0 * HID];
static __device__ int   g_cnt[N_NODES];
static __device__ int   g_off[N_NODES + 1];
static __device__ int   g_cur[N_NODES];
static __device__ int   g_order[N_EDGES];
static __device__ int   g_jidx[M0];
static __device__ float g_jval[M0];

// ---------------- tiny helpers ------------------------------------------------
__device__ __forceinline__ uint32_t f2tf(float x) {
    uint32_t r; asm("cvt.rna.tf32.f32 %0, %1;" : "=r"(r) : "f"(x)); return r;
}
__device__ __forceinline__ float tfbits(float x) {
    return __uint_as_float(f2tf(x));
}
__device__ __forceinline__ void mma_tf32(float* d,
    uint32_t a0, uint32_t a1, uint32_t a2, uint32_t a3,
    uint32_t b0, uint32_t b1)
{
    asm volatile(
        "mma.sync.aligned.m16n8k8.row.col.f32.tf32.tf32.f32 "
        "{%0,%1,%2,%3}, {%4,%5,%6,%7}, {%8,%9}, {%0,%1,%2,%3};"
        : "+f"(d[0]), "+f"(d[1]), "+f"(d[2]), "+f"(d[3])
        : "r"(a0), "r"(a1), "r"(a2), "r"(a3), "r"(b0), "r"(b1));
}
__device__ __forceinline__ void ffma2(unsigned long long& d,
                                      unsigned long long a, unsigned long long b)
{
    asm("fma.rn.f32x2 %0, %1, %2, %0;" : "+l"(d) : "l"(a), "l"(b));
}
__device__ __forceinline__ unsigned long long packf2(float lo, float hi) {
    unsigned long long u;
    asm("mov.b64 %0, {%1,%2};" : "=l"(u) : "f"(lo), "f"(hi));
    return u;
}
__device__ __forceinline__ float2 unpackf2(unsigned long long u) {
    float lo, hi;
    asm("mov.b64 {%0,%1}, %2;" : "=f"(lo), "=f"(hi) : "l"(u));
    return make_float2(lo, hi);
}

// ---------------- prep / CSR ---------------------------------------------------
__global__ void k_prep(const float* __restrict__ to_m) {
    int idx = blockIdx.x * 1024 + threadIdx.x;
    if (idx < N_NODES) g_cnt[idx] = 0;
    if (idx == 0) {
        for (int m = 0; m < M0; m++) {
            int best = 0; float bv = 0.f;
            for (int l = 0; l < NALL; l++) {
                float v = to_m[m * NALL + l];
                if (fabsf(v) > fabsf(bv)) { bv = v; best = l; }
            }
            g_jidx[m] = best;
            g_jval[m] = bv;
        }
    }
}
__global__ void k_count(const int* __restrict__ eidx) {
    int e = blockIdx.x * 256 + threadIdx.x;
    atomicAdd(&g_cnt[eidx[N_EDGES + e]], 1);
}
__global__ void k_scan() {
    __shared__ int s[N_NODES];
    __shared__ int tot[256];
    const int t = threadIdx.x;
    for (int i = t; i < N_NODES; i += 256) s[i] = g_cnt[i];
    __syncthreads();
    const int base = t * 7;
    int sum = 0;
    for (int i = 0; i < 7; i++) {
        int idx = base + i;
        if (idx < N_NODES) { int v = s[idx]; s[idx] = sum; sum += v; }
    }
    tot[t] = sum;
    __syncthreads();
    if (t == 0) {
        int r = 0;
        for (int i = 0; i < 256; i++) { int v = tot[i]; tot[i] = r; r += v; }
        g_off[N_NODES] = r;
    }
    __syncthreads();
    const int b = tot[t];
    for (int i = 0; i < 7; i++) {
        int idx = base + i;
        if (idx < N_NODES) { int o = s[idx] + b; g_off[idx] = o; g_cur[idx] = o; }
    }
}
__global__ void k_scatter(const int* __restrict__ eidx) {
    int e = blockIdx.x * 256 + threadIdx.x;
    int n = eidx[N_EDGES + e];
    int p = atomicAdd(&g_cur[n], 1);
    g_order[p] = e;
}

// ---------------- tensor-core MLP ----------------------------------------------
// 128 edges per block (M=128), 256 threads = 8 warps; warp w owns rows [16w,16w+16).
// tf32 mma m16n8k8; acc[64] covers the warp's 16 rows x 128 cols.
#define SH_OFF   0
#define SB_OFF   16896
#define BI_OFF   21120
#define IX_OFF   22784
#define SMEM_FLOATS 23040
#define SMEM_BYTES  (SMEM_FLOATS * 4)

extern __shared__ float smf[];

__device__ __forceinline__ void mma_chunk(const uint32_t* __restrict__ sAu, int astride,
                                          const uint32_t* __restrict__ sBu,
                                          float* acc, int qr, int qc)
{
#pragma unroll
    for (int ks = 0; ks < 4; ks++) {
        const int kc = ks * 8;
        uint32_t a0 = sAu[ qr      * astride + kc + qc    ];
        uint32_t a1 = sAu[(qr + 8) * astride + kc + qc    ];
        uint32_t a2 = sAu[ qr      * astride + kc + qc + 4];
        uint32_t a3 = sAu[(qr + 8) * astride + kc + qc + 4];
#pragma unroll
        for (int nt = 0; nt < 16; nt++) {
            uint32_t b0 = sBu[(kc + qc)     * 132 + nt * 8 + qr];
            uint32_t b1 = sBu[(kc + qc + 4) * 132 + nt * 8 + qr];
            mma_tf32(acc + nt * 4, a0, a1, a2, a3, b0, b1);
        }
    }
}

__device__ __forceinline__ void stage_w(const float* __restrict__ w, int ldw,
                                        int c0, int woff, float* sB, int t)
{
    const int k  = t >> 3;
    const int nb = (t & 7) * 16;
    const float* src = w + (size_t)(c0 + k) * ldw + woff + nb;
#pragma unroll
    for (int j = 0; j < 4; j++) {
        float4 v = *(const float4*)(src + j * 4);
        float4 c = make_float4(tfbits(v.x), tfbits(v.y), tfbits(v.z), tfbits(v.w));
        *(float4*)(sB + k * 132 + nb + j * 4) = c;
    }
}

__device__ __forceinline__ void ln_silu(float* acc, const float* bias,
                                        const float* gamma, const float* beta,
                                        float* sHrow, int qr, int qc)
{
    float s0 = 0.f, s1 = 0.f, q0 = 0.f, q1 = 0.f;
#pragma unroll
    for (int nt = 0; nt < 16; nt++) {
        int col = nt * 8 + qc * 2;
        float bx = bias[col], by = bias[col + 1];
        float v0 = acc[nt*4+0] + bx, v1 = acc[nt*4+1] + by;
        float v2 = acc[nt*4+2] + bx, v3 = acc[nt*4+3] + by;
        acc[nt*4+0] = v0; acc[nt*4+1] = v1; acc[nt*4+2] = v2; acc[nt*4+3] = v3;
        s0 += v0 + v1; q0 += v0*v0 + v1*v1;
        s1 += v2 + v3; q1 += v2*v2 + v3*v3;
    }
    s0 += __shfl_xor_sync(0xffffffffu, s0, 1); s0 += __shfl_xor_sync(0xffffffffu, s0, 2);
    q0 += __shfl_xor_sync(0xffffffffu, q0, 1); q0 += __shfl_xor_sync(0xffffffffu, q0, 2);
    s1 += __shfl_xor_sync(0xffffffffu, s1, 1); s1 += __shfl_xor_sync(0xffffffffu, s1, 2);
    q1 += __shfl_xor_sync(0xffffffffu, q1, 1); q1 += __shfl_xor_sync(0xffffffffu, q1, 2);
    const float inv = 1.f / 128.f;
    float mu0 = s0 * inv, var0 = q0 * inv - mu0 * mu0, rs0 = rsqrtf(var0 + 1e-5f);
    float mu1 = s1 * inv, var1 = q1 * inv - mu1 * mu1, rs1 = rsqrtf(var1 + 1e-5f);
#pragma unroll
    for (int nt = 0; nt < 16; nt++) {
        int col = nt * 8 + qc * 2;
        float ga = gamma[col], gb = gamma[col + 1];
        float ba = beta[col],  bb = beta[col + 1];
        float h0 = (acc[nt*4+0] - mu0) * rs0 * ga + ba;
        float h1 = (acc[nt*4+1] - mu0) * rs0 * gb + bb;
        float h2 = (acc[nt*4+2] - mu1) * rs1 * ga + ba;
        float h3 = (acc[nt*4+3] - mu1) * rs1 * gb + bb;
        h0 = h0 / (1.f + __expf(-h0));
        h1 = h1 / (1.f + __expf(-h1));
        h2 = h2 / (1.f + __expf(-h2));
        h3 = h3 / (1.f + __expf(-h3));
        *(float2*)(sHrow +  qr      * 132 + col) = make_float2(tfbits(h0), tfbits(h1));
        *(float2*)(sHrow + (qr + 8) * 132 + col) = make_float2(tfbits(h2), tfbits(h3));
    }
}

__global__ __launch_bounds__(256, 2) void k_mlp(
    const float* __restrict__ dist, const int* __restrict__ eidx,
    const int* __restrict__ anum,
    const float* __restrict__ srcT, const float* __restrict__ tgtT,
    const float* __restrict__ w1, const float* __restrict__ b1,
    const float* __restrict__ g1, const float* __restrict__ be1,
    const float* __restrict__ w2, const float* __restrict__ b2,
    const float* __restrict__ g2, const float* __restrict__ be2,
    const float* __restrict__ w3, const float* __restrict__ b3)
{
    float* sH    = smf + SH_OFF;     // 128 x 132
    float* sB    = smf + SB_OFF;     // 32 x 132
    float* sBias = smf + BI_OFF;
    int*   s_src = (int*)(smf + IX_OFF);
    int*   s_tgt = s_src + 128;

    const int t    = threadIdx.x;
    const int e0   = blockIdx.x * 128;
    const int lane = t & 31;
    const int qr   = lane >> 2, qc = lane & 3;
    const int wRow = (t >> 5) * 16;

    if (t < 128) {
        s_src[t] = anum[eidx[e0 + t]];
        s_tgt[t] = anum[eidx[N_EDGES + e0 + t]];
        sBias[t]        = b1[t];  sBias[128 + t]  = g1[t];  sBias[256 + t] = be1[t];
        sBias[384 + t]  = b2[t];  sBias[512 + t]  = g2[t];  sBias[640 + t] = be2[t];
    }
    for (int i = t; i < 896; i += 256) sBias[768 + i] = b3[i];
    __syncthreads();

    const uint32_t* sHu = (const uint32_t*)sH;
    const uint32_t* sBu = (const uint32_t*)sB;
    float acc[64];

    // ===== GEMM1: x[128,768] @ w1[768,128] (x staged into sA = sH base) =====
#pragma unroll
    for (int i = 0; i < 64; i++) acc[i] = 0.f;
    for (int ch = 0; ch < 24; ch++) {
        const int c0 = ch * 32;
        {
            const int row = t >> 1;
            const int cb  = (t & 1) * 16;
            const float* src;
            if (c0 < 512)       src = dist + (size_t)(e0 + row) * 512 + c0 + cb;
            else if (c0 < 640)  src = srcT + (size_t)s_src[row] * 128 + (c0 - 512) + cb;
            else                src = tgtT + (size_t)s_tgt[row] * 128 + (c0 - 640) + cb;
#pragma unroll
            for (int j = 0; j < 4; j++) {
                float4 v = *(const float4*)(src + j * 4);
                float4 c = make_float4(tfbits(v.x), tfbits(v.y), tfbits(v.z), tfbits(v.w));
                *(float4*)(sH + row * 36 + cb + j * 4) = c;
            }
        }
        stage_w(w1, 128, c0, 0, sB, t);
        __syncthreads();
        mma_chunk(sHu + wRow * 36, 36, sBu, acc, qr, qc);
        __syncthreads();
    }
    ln_silu(acc, sBias + 0, sBias + 128, sBias + 256, sH + wRow * 132, qr, qc);
    __syncthreads();

    // ===== GEMM2: h1[128,128] @ w2[128,128] =====
#pragma unroll
    for (int i = 0; i < 64; i++) acc[i] = 0.f;
    for (int ch = 0; ch < 4; ch++) {
        const int c0 = ch * 32;
        stage_w(w2, 128, c0, 0, sB, t);
        __syncthreads();
        // FIX: A operand must advance along K with the chunk (+ c0)
        mma_chunk(sHu + wRow * 132 + c0, 132, sBu, acc, qr, qc);
        __syncthreads();
    }
    ln_silu(acc, sBias + 384, sBias + 512, sBias + 640, sH + wRow * 132, qr, qc);
    __syncthreads();

    // ===== GEMM3: h2[128,128] @ w3[128,896], looped over 7 output slabs =====
    for (int m = 0; m < M0; m++) {
#pragma unroll
        for (int i = 0; i < 64; i++) acc[i] = 0.f;
        for (int ch = 0; ch < 4; ch++) {
            const int c0 = ch * 32;
            stage_w(w3, 896, c0, m * 128, sB, t);
            __syncthreads();
            // FIX: same K-offset on A
            mma_chunk(sHu + wRow * 132 + c0, 132, sBu, acc, qr, qc);
            __syncthreads();
        }
#pragma unroll
        for (int nt = 0; nt < 16; nt++) {
            const int col = nt * 8 + qc * 2;
            const float bx = sBias[768 + m * 128 + col];
            const float by = sBias[768 + m * 128 + col + 1];
            const size_t eA = (size_t)(e0 + wRow + qr);
            const size_t eB = eA + 8;
            *(float2*)(g_x0 + (eA * M0 + m) * 128 + col) =
                make_float2(acc[nt*4+0] + bx, acc[nt*4+1] + by);
            *(float2*)(g_x0 + (eB * M0 + m) * 128 + col) =
                make_float2(acc[nt*4+2] + bx, acc[nt*4+3] + by);
        }
    }
}

// ---------------- node-centric wigner contraction + reduce -----------------------
__global__ __launch_bounds__(128, 3) void k_node(
    const float* __restrict__ wig, float* __restrict__ out)
{
    __shared__ __align__(16) float2 sW[2][2][NSPH * 8];
    __shared__ __align__(16) float2 sRed[NSPH * 64];

    const int n  = blockIdx.x;
    const int t  = threadIdx.x;
    const int g  = t >> 6;
    const int gt = t & 63;

    int   jml[M0];
    float jvl[M0];
#pragma unroll
    for (int m = 0; m < M0; m++) { jml[m] = g_jidx[m]; jvl[m] = g_jval[m]; }

    const int s0  = g_off[n];
    const int cnt = g_off[n + 1] - s0;
    const int nIter = (cnt + 1) >> 1;

    unsigned long long accu[NSPH];
#pragma unroll
    for (int i = 0; i < NSPH; i++) accu[i] = 0ull;

    int eCur = -1;
    float pv[6];
    if (g < cnt) {
        eCur = g_order[s0 + g];
        const float* wb = wig + (size_t)eCur * WROW;
#pragma unroll
        for (int j = 0; j < 6; j++) {
            int idx = gt + j * 64;
            if (idx < 343) pv[j] = wb[(idx / 7) * NALL + jml[idx % 7]];
        }
#pragma unroll
        for (int j = 0; j < 6; j++) {
            int idx = gt + j * 64;
            if (idx < 343) sW[g][0][(idx / 7) * 8 + (idx % 7)] = make_float2(pv[j], pv[j]);
        }
    }
    __syncthreads();

    int cur = 0;
    for (int ii = 0; ii < nIter; ii++) {
        const int posn = 2 * (ii + 1) + g;
        int eNext = -1;
        if (posn < cnt) {
            eNext = g_order[s0 + posn];
            const float* wb = wig + (size_t)eNext * WROW;
#pragma unroll
            for (int j = 0; j < 6; j++) {
                int idx = gt + j * 64;
                if (idx < 343) pv[j] = wb[(idx / 7) * NALL + jml[idx % 7]];
            }
        }
        if (eCur >= 0) {
            unsigned long long xvu[M0];
            const float2* x0p = (const float2*)(g_x0 + (size_t)eCur * M0 * HID) + gt;
#pragma unroll
            for (int m = 0; m < M0; m++) {
                float2 x = x0p[m * 64];
                xvu[m] = packf2(x.x * jvl[m], x.y * jvl[m]);
            }
            const ulonglong2* wp = (const ulonglong2*)sW[g][cur];
#pragma unroll
            for (int i = 0; i < NSPH; i++) {
                ulonglong2 w01 = wp[i * 4 + 0];
                ulonglong2 w23 = wp[i * 4 + 1];
                ulonglong2 w45 = wp[i * 4 + 2];
                ulonglong2 w6p = wp[i * 4 + 3];
                ffma2(accu[i], w01.x, xvu[0]);
                ffma2(accu[i], w01.y, xvu[1]);
                ffma2(accu[i], w23.x, xvu[2]);
                ffma2(accu[i], w23.y, xvu[3]);
                ffma2(accu[i], w45.x, xvu[4]);
                ffma2(accu[i], w45.y, xvu[5]);
                ffma2(accu[i], w6p.x, xvu[6]);
            }
        }
        __syncthreads();
        if (eNext >= 0) {
#pragma unroll
            for (int j = 0; j < 6; j++) {
                int idx = gt + j * 64;
                if (idx < 343) sW[g][cur ^ 1][(idx / 7) * 8 + (idx % 7)] = make_float2(pv[j], pv[j]);
            }
        }
        __syncthreads();
        cur ^= 1;
        eCur = eNext;
    }

    if (g == 1) {
#pragma unroll
        for (int i = 0; i < NSPH; i++) sRed[i * 64 + gt] = unpackf2(accu[i]);
    }
    __syncthreads();
    if (g == 0) {
        const float sc = (float)(1.0 / 23.395238876342773);
        float2* outp = (float2*)out;
#pragma unroll
        for (int i = 0; i < NSPH; i++) {
            float2 r = sRed[i * 64 + gt];
            float2 a = unpackf2(accu[i]);
            outp[((size_t)n * NSPH + i) * 64 + gt] =
                make_float2((a.x + r.x) * sc, (a.y + r.y) * sc);
        }
    }
}

// ---------------- launch ----------------------------------------------------------
extern "C" void kernel_launch(void* const* d_in, const int* in_sizes, int n_in,
                              void* d_out, int out_size)
{
    (void)in_sizes; (void)n_in; (void)out_size;
    const int*   anum = (const int*)  d_in[0];
    const float* dist = (const float*)d_in[1];
    const int*   eidx = (const int*)  d_in[2];
    const float* srcT = (const float*)d_in[3];
    const float* tgtT = (const float*)d_in[4];
    const float* w1   = (const float*)d_in[5];
    const float* b1   = (const float*)d_in[6];
    const float* g1   = (const float*)d_in[7];
    const float* be1  = (const float*)d_in[8];
    const float* w2   = (const float*)d_in[9];
    const float* b2   = (const float*)d_in[10];
    const float* g2   = (const float*)d_in[11];
    const float* be2  = (const float*)d_in[12];
    const float* w3   = (const float*)d_in[13];
    const float* b3   = (const float*)d_in[14];
    const float* to_m = (const float*)d_in[15];
    const float* wig  = (const float*)d_in[16];
    float* out = (float*)d_out;

    cudaFuncSetAttribute(k_mlp, cudaFuncAttributeMaxDynamicSharedMemorySize, SMEM_BYTES);

    k_prep<<<2, 1024>>>(to_m);
    k_count<<<N_EDGES / 256, 256>>>(eidx);
    k_scan<<<1, 256>>>();
    k_scatter<<<N_EDGES / 256, 256>>>(eidx);
    k_mlp<<<N_EDGES / 128, 256, SMEM_BYTES>>>(dist, eidx, anum, srcT, tgtT,
                                              w1, b1, g1, be1, w2, b2, g2, be2, w3, b3);
    k_node<<<N_NODES, 128>>>(wig, out);
}

// round 10
// speedup vs baseline: 2.1834x; 1.5405x over previous
#include <cuda_runtime.h>
#include <cuda_fp16.h>
#include <math.h>
#include <stdint.h>

#define N_EDGES 32000
#define N_NODES 1600
#define HID     128
#define DIN     768
#define M0      7
#define NSPH    49
#define NALL    29
#define WROW    (NSPH * NALL)      // 1421
#define OUT_PER_NODE (NSPH * HID)  // 6272
#define NBLK    (N_EDGES / 128)    // 250

// ---------------- device scratch ---------------------------------------------
static __device__ __align__(256) float g_x0[(size_t)N_EDGES * M0 * HID];
static __device__ int   g_cnt[N_NODES];
static __device__ int   g_off[N_NODES + 1];
static __device__ int   g_cur[N_NODES];
static __device__ int   g_order[N_EDGES];
static __device__ int   g_jidx[M0];
static __device__ float g_jval[M0];
// 28 pre-swizzled fp16 B tiles ([n=128][k=64], SW128 images, 16KB each):
//   0..11 : w1^T   12..13 : w2^T   14..27 : w3^T (7 slabs x 2 k-halves)
static __device__ __align__(1024) __half g_wt16[28 * 8192];
// pre-swizzled fp16 A tiles: [block 250][tile 12][16KB image]
static __device__ __align__(1024) uint4  g_xh4[(size_t)NBLK * 12 * 1024];

// byte swizzle inside a [128 rows x 128B] tile image (SW128)
#define SWZ(b) ((uint32_t)(b) ^ ((((uint32_t)(b)) >> 3) & 0x70))

// ---------------- tiny helpers ------------------------------------------------
__device__ __forceinline__ uint32_t smem_u32(const void* p) {
    uint32_t a;
    asm("{ .reg .u64 t; cvta.to.shared.u64 t, %1; cvt.u32.u64 %0, t; }" : "=r"(a) : "l"(p));
    return a;
}
__device__ __forceinline__ void ffma2(unsigned long long& d,
                                      unsigned long long a, unsigned long long b)
{
    asm("fma.rn.f32x2 %0, %1, %2, %0;" : "+l"(d) : "l"(a), "l"(b));
}
__device__ __forceinline__ unsigned long long packf2(float lo, float hi) {
    unsigned long long u;
    asm("mov.b64 %0, {%1,%2};" : "=l"(u) : "f"(lo), "f"(hi));
    return u;
}
__device__ __forceinline__ float2 unpackf2(unsigned long long u) {
    float lo, hi;
    asm("mov.b64 {%0,%1}, %2;" : "=f"(lo), "=f"(hi) : "l"(u));
    return make_float2(lo, hi);
}

#define LDSM_X4(r0, r1, r2, r3, addr) \
    asm volatile("ldmatrix.sync.aligned.m8n8.x4.shared.b16 {%0,%1,%2,%3}, [%4];" \
        : "=r"(r0), "=r"(r1), "=r"(r2), "=r"(r3) : "r"(addr))

#define MMA16(ac, a0, a1, a2, a3, b0, b1) \
    asm volatile("mma.sync.aligned.m16n8k16.row.col.f32.f16.f16.f32 " \
        "{%0,%1,%2,%3}, {%4,%5,%6,%7}, {%8,%9}, {%0,%1,%2,%3};" \
        : "+f"((ac)[0]), "+f"((ac)[1]), "+f"((ac)[2]), "+f"((ac)[3]) \
        : "r"(a0), "r"(a1), "r"(a2), "r"(a3), "r"(b0), "r"(b1))

__device__ __forceinline__ void cpa16(uint32_t s, const void* g) {
    asm volatile("cp.async.cg.shared.global [%0], [%1], 16;" :: "r"(s), "l"(g));
}
#define CPA_COMMIT() asm volatile("cp.async.commit_group;" ::: "memory")
#define CPA_WAIT1()  asm volatile("cp.async.wait_group 1;" ::: "memory")

// ---------------- prep / CSR ---------------------------------------------------
__global__ void k_prep(const float* __restrict__ to_m) {
    int idx = blockIdx.x * 1024 + threadIdx.x;
    if (idx < N_NODES) g_cnt[idx] = 0;
    if (idx == 0) {
        for (int m = 0; m < M0; m++) {
            int best = 0; float bv = 0.f;
            for (int l = 0; l < NALL; l++) {
                float v = to_m[m * NALL + l];
                if (fabsf(v) > fabsf(bv)) { bv = v; best = l; }
            }
            g_jidx[m] = best;
            g_jval[m] = bv;
        }
    }
}

// gather x = [dist | src | tgt] -> fp16, SW128-swizzled A-tile images
__global__ void k_xprep(const float* __restrict__ dist, const int* __restrict__ eidx,
                        const int* __restrict__ anum,
                        const float* __restrict__ srcT, const float* __restrict__ tgtT)
{
    int idx = blockIdx.x * 256 + threadIdx.x;   // 32000*96
    int e    = idx / 96;
    int col0 = (idx % 96) * 8;
    float v[8];
    if (col0 < 512) {
        const float4* s = (const float4*)(dist + (size_t)e * 512 + col0);
        float4 x = s[0], y = s[1];
        v[0]=x.x; v[1]=x.y; v[2]=x.z; v[3]=x.w; v[4]=y.x; v[5]=y.y; v[6]=y.z; v[7]=y.w;
    } else if (col0 < 640) {
        int a = anum[eidx[e]];
        const float4* s = (const float4*)(srcT + (size_t)a * 128 + (col0 - 512));
        float4 x = s[0], y = s[1];
        v[0]=x.x; v[1]=x.y; v[2]=x.z; v[3]=x.w; v[4]=y.x; v[5]=y.y; v[6]=y.z; v[7]=y.w;
    } else {
        int a = anum[eidx[N_EDGES + e]];
        const float4* s = (const float4*)(tgtT + (size_t)a * 128 + (col0 - 640));
        float4 x = s[0], y = s[1];
        v[0]=x.x; v[1]=x.y; v[2]=x.z; v[3]=x.w; v[4]=y.x; v[5]=y.y; v[6]=y.z; v[7]=y.w;
    }
    __half2 h[4];
#pragma unroll
    for (int i = 0; i < 4; i++) h[i] = __floats2half2_rn(v[2 * i], v[2 * i + 1]);
    int blk = e >> 7, ti = col0 >> 6;
    uint32_t byte = SWZ((e & 127) * 128 + (col0 & 63) * 2);
    *(uint4*)((char*)g_xh4 + ((size_t)(blk * 12 + ti)) * 16384 + byte) = *(uint4*)h;
}

// weights -> [n][k] fp16, SW128-swizzled B-tile images
__global__ void k_wprep(const float* __restrict__ w1, const float* __restrict__ w2,
                        const float* __restrict__ w3)
{
    int idx = blockIdx.x * 256 + threadIdx.x;   // 28*8192
    int tile = idx >> 13;
    int r    = idx & 8191;
    int n = r >> 6, k = r & 63;
    float v;
    if (tile < 12)      v = w1[(size_t)(tile * 64 + k) * 128 + n];
    else if (tile < 14) v = w2[(size_t)((tile - 12) * 64 + k) * 128 + n];
    else {
        int mt = tile - 14, m = mt >> 1, hf = mt & 1;
        v = w3[(size_t)(hf * 64 + k) * 896 + m * 128 + n];
    }
    uint32_t byte = SWZ(n * 128 + k * 2);
    *(__half*)((char*)g_wt16 + (size_t)tile * 16384 + byte) = __float2half_rn(v);
}

__global__ void k_count(const int* __restrict__ eidx) {
    int e = blockIdx.x * 256 + threadIdx.x;
    atomicAdd(&g_cnt[eidx[N_EDGES + e]], 1);
}
__global__ void k_scan() {
    __shared__ int s[N_NODES];
    __shared__ int tot[256];
    const int t = threadIdx.x;
    for (int i = t; i < N_NODES; i += 256) s[i] = g_cnt[i];
    __syncthreads();
    const int base = t * 7;
    int sum = 0;
    for (int i = 0; i < 7; i++) {
        int idx = base + i;
        if (idx < N_NODES) { int v = s[idx]; s[idx] = sum; sum += v; }
    }
    tot[t] = sum;
    __syncthreads();
    if (t == 0) {
        int r = 0;
        for (int i = 0; i < 256; i++) { int v = tot[i]; tot[i] = r; r += v; }
        g_off[N_NODES] = r;
    }
    __syncthreads();
    const int b = tot[t];
    for (int i = 0; i < 7; i++) {
        int idx = base + i;
        if (idx < N_NODES) { int o = s[idx] + b; g_off[idx] = o; g_cur[idx] = o; }
    }
}
__global__ void k_scatter(const int* __restrict__ eidx) {
    int e = blockIdx.x * 256 + threadIdx.x;
    int n = eidx[N_EDGES + e];
    int p = atomicAdd(&g_cur[n], 1);
    g_order[p] = e;
}

// ---------------- fp16 mma MLP ----------------------------------------------------
// smem byte offsets from 1024-aligned base
#define SM_HB   0          // 2 x 16KB : h tiles (A for GEMM2/3)
#define SM_AB   32768      // 2 x 16KB : streamed A tiles
#define SM_BB   65536      // 2 x 16KB : streamed B tiles
#define SM_PAR  98304      // 1664 floats
#define SMEM_MLP (98304 + 6656 + 1024)

extern __shared__ float smf[];

__device__ __forceinline__ void compute_tile(uint32_t abase, uint32_t bbase,
                                             float* acc, int wRow, int lane)
{
    const int mid = lane >> 3, r8 = lane & 7;
    const uint32_t a_off = (uint32_t)((wRow + (mid & 1) * 8 + r8) * 128 + (mid >> 1) * 16);
    const uint32_t b_hoff = (uint32_t)((mid & 1) * 16);
    const int jadd = mid >> 1;
#pragma unroll
    for (int ks = 0; ks < 4; ks++) {
        const uint32_t colb = ks * 32;
        uint32_t a0, a1, a2, a3;
        LDSM_X4(a0, a1, a2, a3, abase + SWZ(a_off + colb));
#pragma unroll
        for (int j = 0; j < 16; j += 2) {
            uint32_t b0, b1, b2, b3;
            uint32_t baddr = bbase + SWZ((uint32_t)(((j + jadd) * 8 + r8) * 128) + colb + b_hoff);
            LDSM_X4(b0, b1, b2, b3, baddr);
            MMA16(acc + j * 4,       a0, a1, a2, a3, b0, b1);
            MMA16(acc + (j + 1) * 4, a0, a1, a2, a3, b2, b3);
        }
    }
}

__global__ __launch_bounds__(256, 2) void k_mlp(
    const float* __restrict__ b1, const float* __restrict__ g1, const float* __restrict__ be1,
    const float* __restrict__ b2, const float* __restrict__ g2, const float* __restrict__ be2,
    const float* __restrict__ b3)
{
    const uint32_t base0 = smem_u32(smf);
    const uint32_t base  = (base0 + 1023) & ~1023u;
    char* smc = (char*)smf + (base - base0);

    const int t    = threadIdx.x;
    const int lane = t & 31;
    const int wid  = t >> 5;
    const int wRow = wid * 16;
    const int e0   = blockIdx.x * 128;
    const int qr   = lane >> 2, qc = lane & 3;

    const uint32_t hb = base + SM_HB;
    const uint32_t ab = base + SM_AB;
    const uint32_t bb = base + SM_BB;
    float* par = (float*)(smc + SM_PAR);

    if (t < 128) {
        par[t]       = b1[t]; par[128 + t] = g1[t]; par[256 + t] = be1[t];
        par[384 + t] = b2[t]; par[512 + t] = g2[t]; par[640 + t] = be2[t];
    }
    for (int i = t; i < 896; i += 256) par[768 + i] = b3[i];

    // issue helpers: linear 16KB image copies (64B per thread)
    auto issueA = [&](int ti, uint32_t buf) {
        const char* src = (const char*)g_xh4 + ((size_t)(blockIdx.x * 12 + ti)) * 16384 + t * 16;
#pragma unroll
        for (int j = 0; j < 4; j++) cpa16(buf + t * 16 + j * 4096, src + j * 4096);
    };
    auto issueB = [&](int ti, uint32_t buf) {
        const char* src = (const char*)g_wt16 + (size_t)ti * 16384 + t * 16;
#pragma unroll
        for (int j = 0; j < 4; j++) cpa16(buf + t * 16 + j * 4096, src + j * 4096);
    };

    // prologue: tiles 0,1 in flight
    issueA(0, ab);         issueB(0, bb);         CPA_COMMIT();
    issueA(1, ab + 16384); issueB(1, bb + 16384); CPA_COMMIT();

    float acc[64];
#pragma unroll
    for (int i = 0; i < 64; i++) acc[i] = 0.f;

    // LN + SiLU epilogue: acc (bias added in place) -> fp16 swizzled h tiles
    auto ln_ep = [&](int pbase) {
        float s0 = 0.f, q0 = 0.f, s1 = 0.f, q1 = 0.f;
#pragma unroll
        for (int nt = 0; nt < 16; nt++) {
            const int col = nt * 8 + qc * 2;
            float bx = par[pbase + col], by = par[pbase + col + 1];
            float v0 = acc[nt*4+0] + bx, v1 = acc[nt*4+1] + by;
            float v2 = acc[nt*4+2] + bx, v3 = acc[nt*4+3] + by;
            acc[nt*4+0] = v0; acc[nt*4+1] = v1; acc[nt*4+2] = v2; acc[nt*4+3] = v3;
            s0 += v0 + v1; q0 += v0*v0 + v1*v1;
            s1 += v2 + v3; q1 += v2*v2 + v3*v3;
        }
        s0 += __shfl_xor_sync(0xffffffffu, s0, 1); s0 += __shfl_xor_sync(0xffffffffu, s0, 2);
        q0 += __shfl_xor_sync(0xffffffffu, q0, 1); q0 += __shfl_xor_sync(0xffffffffu, q0, 2);
        s1 += __shfl_xor_sync(0xffffffffu, s1, 1); s1 += __shfl_xor_sync(0xffffffffu, s1, 2);
        q1 += __shfl_xor_sync(0xffffffffu, q1, 1); q1 += __shfl_xor_sync(0xffffffffu, q1, 2);
        const float inv = 1.f / 128.f;
        float mu0 = s0 * inv, var0 = q0 * inv - mu0 * mu0, rs0 = rsqrtf(var0 + 1e-5f);
        float mu1 = s1 * inv, var1 = q1 * inv - mu1 * mu1, rs1 = rsqrtf(var1 + 1e-5f);
        const int r0 = wRow + qr, r1 = r0 + 8;
#pragma unroll
        for (int nt = 0; nt < 16; nt++) {
            const int col = nt * 8 + qc * 2;
            float ga = par[pbase + 128 + col], gb = par[pbase + 128 + col + 1];
            float ba = par[pbase + 256 + col], bbv = par[pbase + 256 + col + 1];
            float h0 = (acc[nt*4+0] - mu0) * rs0 * ga + ba;
            float h1 = (acc[nt*4+1] - mu0) * rs0 * gb + bbv;
            float h2 = (acc[nt*4+2] - mu1) * rs1 * ga + ba;
            float h3 = (acc[nt*4+3] - mu1) * rs1 * gb + bbv;
            h0 = h0 / (1.f + __expf(-h0));
            h1 = h1 / (1.f + __expf(-h1));
            h2 = h2 / (1.f + __expf(-h2));
            h3 = h3 / (1.f + __expf(-h3));
            __half2 p0 = __floats2half2_rn(h0, h1);
            __half2 p1 = __floats2half2_rn(h2, h3);
            const uint32_t tb = hb + (col >> 6) * 16384;
            const uint32_t cb = (col & 63) * 2;
            asm volatile("st.shared.u32 [%0], %1;"
                :: "r"(tb + SWZ(r0 * 128 + cb)), "r"(*(uint32_t*)&p0) : "memory");
            asm volatile("st.shared.u32 [%0], %1;"
                :: "r"(tb + SWZ(r1 * 128 + cb)), "r"(*(uint32_t*)&p1) : "memory");
        }
#pragma unroll
        for (int i = 0; i < 64; i++) acc[i] = 0.f;
        __syncthreads();
    };

    // ===== GEMM1: tiles 0..11 (A streamed, B streamed) =====
    for (int ti = 0; ti < 12; ti++) {
        const uint32_t p = (ti & 1) * 16384;
        CPA_WAIT1();
        __syncthreads();
        compute_tile(ab + p, bb + p, acc, wRow, lane);
        __syncthreads();
        if (ti + 2 < 12) issueA(ti + 2, ab + p);
        if (ti + 2 < 28) issueB(ti + 2, bb + p);
        CPA_COMMIT();
    }
    ln_ep(0);

    // ===== GEMM2: B tiles 12,13; A = h tiles =====
    for (int gi = 0; gi < 2; gi++) {
        const int ti = 12 + gi;
        const uint32_t p = (ti & 1) * 16384;
        CPA_WAIT1();
        __syncthreads();
        compute_tile(hb + gi * 16384, bb + p, acc, wRow, lane);
        __syncthreads();
        if (ti + 2 < 28) issueB(ti + 2, bb + p);
        CPA_COMMIT();
    }
    ln_ep(384);

    // ===== GEMM3: 7 slabs x 2 k-halves; B tiles 14..27; A = h tiles =====
    for (int g3 = 0; g3 < 14; g3++) {
        const int m = g3 >> 1, hf = g3 & 1;
        const int ti = 14 + g3;
        const uint32_t p = (ti & 1) * 16384;
        CPA_WAIT1();
        __syncthreads();
        compute_tile(hb + hf * 16384, bb + p, acc, wRow, lane);
        __syncthreads();
        if (ti + 2 < 28) issueB(ti + 2, bb + p);
        CPA_COMMIT();
        if (hf == 1) {
            // epilogue slab m: bias + store x0, zero acc
#pragma unroll
            for (int nt = 0; nt < 16; nt++) {
                const int col = nt * 8 + qc * 2;
                const float bx = par[768 + m * 128 + col];
                const float by = par[768 + m * 128 + col + 1];
                const size_t eA = (size_t)(e0 + wRow + qr);
                const size_t eB = eA + 8;
                *(float2*)(g_x0 + (eA * M0 + m) * 128 + col) =
                    make_float2(acc[nt*4+0] + bx, acc[nt*4+1] + by);
                *(float2*)(g_x0 + (eB * M0 + m) * 128 + col) =
                    make_float2(acc[nt*4+2] + bx, acc[nt*4+3] + by);
            }
#pragma unroll
            for (int i = 0; i < 64; i++) acc[i] = 0.f;
        }
    }
}

// ---------------- node-centric wigner contraction + reduce -----------------------
__global__ __launch_bounds__(128, 3) void k_node(
    const float* __restrict__ wig, float* __restrict__ out)
{
    __shared__ __align__(16) float2 sW[2][2][NSPH * 8];
    __shared__ __align__(16) float2 sRed[NSPH * 64];

    const int n  = blockIdx.x;
    const int t  = threadIdx.x;
    const int g  = t >> 6;
    const int gt = t & 63;

    int   jml[M0];
    float jvl[M0];
#pragma unroll
    for (int m = 0; m < M0; m++) { jml[m] = g_jidx[m]; jvl[m] = g_jval[m]; }

    const int s0  = g_off[n];
    const int cnt = g_off[n + 1] - s0;
    const int nIter = (cnt + 1) >> 1;

    unsigned long long accu[NSPH];
#pragma unroll
    for (int i = 0; i < NSPH; i++) accu[i] = 0ull;

    int eCur = -1;
    float pv[6];
    if (g < cnt) {
        eCur = g_order[s0 + g];
        const float* wb = wig + (size_t)eCur * WROW;
#pragma unroll
        for (int j = 0; j < 6; j++) {
            int idx = gt + j * 64;
            if (idx < 343) pv[j] = wb[(idx / 7) * NALL + jml[idx % 7]];
        }
#pragma unroll
        for (int j = 0; j < 6; j++) {
            int idx = gt + j * 64;
            if (idx < 343) sW[g][0][(idx / 7) * 8 + (idx % 7)] = make_float2(pv[j], pv[j]);
        }
    }
    __syncthreads();

    int cur = 0;
    for (int ii = 0; ii < nIter; ii++) {
        const int posn = 2 * (ii + 1) + g;
        int eNext = -1;
        if (posn < cnt) {
            eNext = g_order[s0 + posn];
            const float* wb = wig + (size_t)eNext * WROW;
#pragma unroll
            for (int j = 0; j < 6; j++) {
                int idx = gt + j * 64;
                if (idx < 343) pv[j] = wb[(idx / 7) * NALL + jml[idx % 7]];
            }
        }
        if (eCur >= 0) {
            unsigned long long xvu[M0];
            const float2* x0p = (const float2*)(g_x0 + (size_t)eCur * M0 * HID) + gt;
#pragma unroll
            for (int m = 0; m < M0; m++) {
                float2 x = x0p[m * 64];
                xvu[m] = packf2(x.x * jvl[m], x.y * jvl[m]);
            }
            const ulonglong2* wp = (const ulonglong2*)sW[g][cur];
#pragma unroll
            for (int i = 0; i < NSPH; i++) {
                ulonglong2 w01 = wp[i * 4 + 0];
                ulonglong2 w23 = wp[i * 4 + 1];
                ulonglong2 w45 = wp[i * 4 + 2];
                ulonglong2 w6p = wp[i * 4 + 3];
                ffma2(accu[i], w01.x, xvu[0]);
                ffma2(accu[i], w01.y, xvu[1]);
                ffma2(accu[i], w23.x, xvu[2]);
                ffma2(accu[i], w23.y, xvu[3]);
                ffma2(accu[i], w45.x, xvu[4]);
                ffma2(accu[i], w45.y, xvu[5]);
                ffma2(accu[i], w6p.x, xvu[6]);
            }
        }
        __syncthreads();
        if (eNext >= 0) {
#pragma unroll
            for (int j = 0; j < 6; j++) {
                int idx = gt + j * 64;
                if (idx < 343) sW[g][cur ^ 1][(idx / 7) * 8 + (idx % 7)] = make_float2(pv[j], pv[j]);
            }
        }
        __syncthreads();
        cur ^= 1;
        eCur = eNext;
    }

    if (g == 1) {
#pragma unroll
        for (int i = 0; i < NSPH; i++) sRed[i * 64 + gt] = unpackf2(accu[i]);
    }
    __syncthreads();
    if (g == 0) {
        const float sc = (float)(1.0 / 23.395238876342773);
        float2* outp = (float2*)out;
#pragma unroll
        for (int i = 0; i < NSPH; i++) {
            float2 r = sRed[i * 64 + gt];
            float2 a = unpackf2(accu[i]);
            outp[((size_t)n * NSPH + i) * 64 + gt] =
                make_float2((a.x + r.x) * sc, (a.y + r.y) * sc);
        }
    }
}

// ---------------- launch ----------------------------------------------------------
extern "C" void kernel_launch(void* const* d_in, const int* in_sizes, int n_in,
                              void* d_out, int out_size)
{
    (void)in_sizes; (void)n_in; (void)out_size;
    const int*   anum = (const int*)  d_in[0];
    const float* dist = (const float*)d_in[1];
    const int*   eidx = (const int*)  d_in[2];
    const float* srcT = (const float*)d_in[3];
    const float* tgtT = (const float*)d_in[4];
    const float* w1   = (const float*)d_in[5];
    const float* b1   = (const float*)d_in[6];
    const float* g1   = (const float*)d_in[7];
    const float* be1  = (const float*)d_in[8];
    const float* w2   = (const float*)d_in[9];
    const float* b2   = (const float*)d_in[10];
    const float* g2   = (const float*)d_in[11];
    const float* be2  = (const float*)d_in[12];
    const float* w3   = (const float*)d_in[13];
    const float* b3   = (const float*)d_in[14];
    const float* to_m = (const float*)d_in[15];
    const float* wig  = (const float*)d_in[16];
    float* out = (float*)d_out;

    cudaFuncSetAttribute(k_mlp, cudaFuncAttributeMaxDynamicSharedMemorySize, SMEM_MLP);

    k_prep<<<2, 1024>>>(to_m);
    k_xprep<<<N_EDGES * 96 / 256, 256>>>(dist, eidx, anum, srcT, tgtT);
    k_wprep<<<28 * 8192 / 256, 256>>>(w1, w2, w3);
    k_count<<<N_EDGES / 256, 256>>>(eidx);
    k_scan<<<1, 256>>>();
    k_scatter<<<N_EDGES / 256, 256>>>(eidx);
    k_mlp<<<NBLK, 256, SMEM_MLP>>>(b1, g1, be1, b2, g2, be2, b3);
    k_node<<<N_NODES, 128>>>(wig, out);
}